// round 5
// baseline (speedup 1.0000x reference)
#include <cuda_runtime.h>

#define L 32768
#define E 1024
#define H 8
#define D 128
#define E4 (E/4)          // 256 float4 per row
#define ROWS 128
#define NBLK (L/ROWS)     // 256 blocks in the big passes
#define RSQRT_D 0.08838834764831845f   // 1/sqrt(128)

// ---------------- device scratch (no allocations allowed) ----------------
__device__ float g_q[E];                      // q projection [E]
__device__ float g_s[H][E];                   // s = (Wk_h^T q_h) * rsqrt(D)
__device__ float g_logits[H][L];              // 1 MB
__device__ float g_stats[2 * H];              // [0..7]=max, [8..15]=1/sum
__device__ float g_partial[NBLK][H][E];       // 8 MB  per-block weighted sums
__device__ float g_partial2[16][H][E];        // 512 KB stage-2 partials
__device__ float g_w[H][E];                   // Σ a_l x_l per head
__device__ float g_attn[E];                   // Wv @ w + bv (concat heads)

__device__ __forceinline__ float warp_sum(float v) {
    v += __shfl_xor_sync(0xffffffffu, v, 16);
    v += __shfl_xor_sync(0xffffffffu, v, 8);
    v += __shfl_xor_sync(0xffffffffu, v, 4);
    v += __shfl_xor_sync(0xffffffffu, v, 2);
    v += __shfl_xor_sync(0xffffffffu, v, 1);
    return v;
}

// ---------------- K1: q[row] = Wq[row,:]·x0 + bq[row] ----------------
// grid 128 x 256 threads; one warp per output row.
__global__ __launch_bounds__(256) void k_qproj(const float4* __restrict__ W4,
                                               const float4* __restrict__ X4,
                                               const float* __restrict__ bias) {
    int warp = threadIdx.x >> 5, lane = threadIdx.x & 31;
    int row = blockIdx.x * 8 + warp;            // 0..1023
    const float4* wr = W4 + (size_t)row * E4;   // rows 0..E-1 = Wq
    float4 a = make_float4(0.f, 0.f, 0.f, 0.f);
    #pragma unroll
    for (int i = 0; i < 8; i++) {
        float4 w = wr[lane + 32 * i];
        float4 x = X4[lane + 32 * i];           // x row 0
        a.x = fmaf(w.x, x.x, a.x);
        a.y = fmaf(w.y, x.y, a.y);
        a.z = fmaf(w.z, x.z, a.z);
        a.w = fmaf(w.w, x.w, a.w);
    }
    float acc = warp_sum((a.x + a.y) + (a.z + a.w));
    if (lane == 0) g_q[row] = acc + bias[row];
}

// ---------------- K2: s[h][e] = rsqrtD * Σ_d Wk[h*D+d][e] * q[h*D+d] ----
// grid 32 (= h*4 + eblock) x 256 threads; coalesced over e.
__global__ __launch_bounds__(256) void k_sproj(const float* __restrict__ W) {
    int h = blockIdx.x >> 2, eb = blockIdx.x & 3;
    int e = eb * 256 + threadIdx.x;
    __shared__ float qsh[D];
    if (threadIdx.x < D) qsh[threadIdx.x] = g_q[h * D + threadIdx.x];
    __syncthreads();
    const float* Wk = W + (size_t)(E + h * D) * E + e;   // k-block rows
    float acc = 0.f;
    #pragma unroll 4
    for (int d = 0; d < D; d++)
        acc = fmaf(Wk[(size_t)d * E], qsh[d], acc);
    g_s[h][e] = acc * RSQRT_D;
}

// ---------------- K3: logits[h][l] = x_l · s_h --------------------------
// grid 256 x 256 threads; warp = head, lane j owns e = {4j+128i}.
__global__ __launch_bounds__(256) void k_logits(const float4* __restrict__ X4) {
    int t = threadIdx.x;
    int h = t >> 5, j = t & 31;
    int row0 = blockIdx.x * ROWS;
    __shared__ float4 xbuf[2][E4];              // 8 KB double buffer
    float4 s[8];
    const float4* S4 = (const float4*)g_s[h];
    #pragma unroll
    for (int i = 0; i < 8; i++) s[i] = S4[j + 32 * i];

    xbuf[0][t] = X4[(size_t)row0 * E4 + t];
    __syncthreads();
    for (int r = 0; r < ROWS; r++) {
        int p = r & 1;
        if (r + 1 < ROWS) xbuf[p ^ 1][t] = X4[(size_t)(row0 + r + 1) * E4 + t];
        float4 a = make_float4(0.f, 0.f, 0.f, 0.f);
        #pragma unroll
        for (int i = 0; i < 8; i++) {
            float4 xv = xbuf[p][j + 32 * i];
            a.x = fmaf(xv.x, s[i].x, a.x);
            a.y = fmaf(xv.y, s[i].y, a.y);
            a.z = fmaf(xv.z, s[i].z, a.z);
            a.w = fmaf(xv.w, s[i].w, a.w);
        }
        float v = warp_sum((a.x + a.y) + (a.z + a.w));
        if (j == 0) g_logits[h][row0 + r] = v;
        __syncthreads();
    }
}

// ---------------- K4: per-head max and 1/sum(exp) ------------------------
// grid 8 x 256 threads, one block per head; two L2-hot sweeps.
__global__ __launch_bounds__(256) void k_stats() {
    int h = blockIdx.x, t = threadIdx.x;
    const float* lg = g_logits[h];
    __shared__ float red[8];
    __shared__ float Msh;

    float m = -1e30f;
    for (int i = t; i < L; i += 256) m = fmaxf(m, lg[i]);
    #pragma unroll
    for (int o = 16; o; o >>= 1) m = fmaxf(m, __shfl_xor_sync(0xffffffffu, m, o));
    if ((t & 31) == 0) red[t >> 5] = m;
    __syncthreads();
    if (t == 0) {
        float mm = red[0];
        for (int w = 1; w < 8; w++) mm = fmaxf(mm, red[w]);
        Msh = mm;
    }
    __syncthreads();
    float M = Msh;

    float s = 0.f;
    for (int i = t; i < L; i += 256) s += __expf(lg[i] - M);
    s = warp_sum(s);
    if ((t & 31) == 0) red[t >> 5] = s;
    __syncthreads();
    if (t == 0) {
        float ss = 0.f;
        for (int w = 0; w < 8; w++) ss += red[w];
        g_stats[h] = M;
        g_stats[8 + h] = 1.0f / ss;
    }
}

// ---------------- K5: per-block partial w_h = Σ_l a_lh x_l ---------------
// grid 256 x 256 threads; warp = head; 32 fp32 accumulators per thread.
__global__ __launch_bounds__(256) void k_wsum(const float4* __restrict__ X4) {
    int t = threadIdx.x;
    int h = t >> 5, j = t & 31;
    int b = blockIdx.x;
    int row0 = b * ROWS;
    __shared__ float4 xbuf[2][E4];              // 8 KB
    __shared__ float ash[H][ROWS];              // 4 KB softmax weights

    #pragma unroll
    for (int i = 0; i < 4; i++) {
        int idx = t + 256 * i;                  // 0..1023
        int hh = idx >> 7, r = idx & 127;
        ash[hh][r] = __expf(g_logits[hh][row0 + r] - g_stats[hh]) * g_stats[8 + hh];
    }
    float4 acc[8];
    #pragma unroll
    for (int i = 0; i < 8; i++) acc[i] = make_float4(0.f, 0.f, 0.f, 0.f);

    xbuf[0][t] = X4[(size_t)row0 * E4 + t];
    __syncthreads();
    for (int r = 0; r < ROWS; r++) {
        int p = r & 1;
        if (r + 1 < ROWS) xbuf[p ^ 1][t] = X4[(size_t)(row0 + r + 1) * E4 + t];
        float a = ash[h][r];                    // broadcast within warp
        #pragma unroll
        for (int i = 0; i < 8; i++) {
            float4 xv = xbuf[p][j + 32 * i];
            acc[i].x = fmaf(a, xv.x, acc[i].x);
            acc[i].y = fmaf(a, xv.y, acc[i].y);
            acc[i].z = fmaf(a, xv.z, acc[i].z);
            acc[i].w = fmaf(a, xv.w, acc[i].w);
        }
        __syncthreads();
    }
    float4* P4 = (float4*)g_partial[b][h];
    #pragma unroll
    for (int i = 0; i < 8; i++) P4[j + 32 * i] = acc[i];
}

// ---------------- K6a/K6b: deterministic 2-stage reduction ---------------
__global__ __launch_bounds__(128) void k_reduce1() {
    // grid (16,16) x 128: x = output chunk (128 float4), y = 16-block group
    int out4 = blockIdx.x * 128 + threadIdx.x;  // 0..2047
    int b0 = blockIdx.y * 16;
    const float4* P4 = (const float4*)g_partial;
    float4 acc = make_float4(0.f, 0.f, 0.f, 0.f);
    #pragma unroll 4
    for (int b = b0; b < b0 + 16; b++) {
        float4 v = P4[(size_t)b * (H * E4) + out4];
        acc.x += v.x; acc.y += v.y; acc.z += v.z; acc.w += v.w;
    }
    ((float4*)g_partial2)[(size_t)blockIdx.y * (H * E4) + out4] = acc;
}

__global__ __launch_bounds__(128) void k_reduce2() {
    // grid 16 x 128
    int out4 = blockIdx.x * 128 + threadIdx.x;  // 0..2047
    const float4* P4 = (const float4*)g_partial2;
    float4 acc = make_float4(0.f, 0.f, 0.f, 0.f);
    #pragma unroll
    for (int b = 0; b < 16; b++) {
        float4 v = P4[(size_t)b * (H * E4) + out4];
        acc.x += v.x; acc.y += v.y; acc.z += v.z; acc.w += v.w;
    }
    ((float4*)g_w)[out4] = acc;
}

// ---------------- K7: attn[row] = Wv[row,:]·w_h + bv[row] ----------------
__global__ __launch_bounds__(256) void k_vproj(const float4* __restrict__ W4,
                                               const float* __restrict__ bias) {
    int warp = threadIdx.x >> 5, lane = threadIdx.x & 31;
    int row = blockIdx.x * 8 + warp;            // 0..1023 (h*D+d)
    int h = row >> 7;
    const float4* wr = W4 + (size_t)(2 * E + row) * E4;   // v-block rows
    const float4* v4 = (const float4*)g_w[h];
    float4 a = make_float4(0.f, 0.f, 0.f, 0.f);
    #pragma unroll
    for (int i = 0; i < 8; i++) {
        float4 w = wr[lane + 32 * i];
        float4 x = v4[lane + 32 * i];
        a.x = fmaf(w.x, x.x, a.x);
        a.y = fmaf(w.y, x.y, a.y);
        a.z = fmaf(w.z, x.z, a.z);
        a.w = fmaf(w.w, x.w, a.w);
    }
    float acc = warp_sum((a.x + a.y) + (a.z + a.w));
    if (lane == 0) g_attn[row] = acc + bias[2 * E + row];
}

// ---------------- K8: out[row] = Wo[row,:]·attn + bo[row] ----------------
__global__ __launch_bounds__(256) void k_oproj(const float4* __restrict__ Wo4,
                                               const float* __restrict__ bo,
                                               float* __restrict__ out) {
    int warp = threadIdx.x >> 5, lane = threadIdx.x & 31;
    int row = blockIdx.x * 8 + warp;            // 0..1023
    const float4* wr = Wo4 + (size_t)row * E4;
    const float4* v4 = (const float4*)g_attn;
    float4 a = make_float4(0.f, 0.f, 0.f, 0.f);
    #pragma unroll
    for (int i = 0; i < 8; i++) {
        float4 w = wr[lane + 32 * i];
        float4 x = v4[lane + 32 * i];
        a.x = fmaf(w.x, x.x, a.x);
        a.y = fmaf(w.y, x.y, a.y);
        a.z = fmaf(w.z, x.z, a.z);
        a.w = fmaf(w.w, x.w, a.w);
    }
    float acc = warp_sum((a.x + a.y) + (a.z + a.w));
    if (lane == 0) out[row] = acc + bo[row];
}

extern "C" void kernel_launch(void* const* d_in, const int* in_sizes, int n_in,
                              void* d_out, int out_size) {
    const float* x   = (const float*)d_in[0];   // [L, E]
    const float* Win = (const float*)d_in[1];   // [3E, E]
    const float* bin = (const float*)d_in[2];   // [3E]
    const float* Wo  = (const float*)d_in[3];   // [E, E]
    const float* bo  = (const float*)d_in[4];   // [E]
    float* out = (float*)d_out;                 // [1, E]

    const float4* X4 = (const float4*)x;
    const float4* Win4 = (const float4*)Win;
    const float4* Wo4 = (const float4*)Wo;

    k_qproj<<<128, 256>>>(Win4, X4, bin);
    k_sproj<<<32, 256>>>(Win);
    k_logits<<<NBLK, 256>>>(X4);
    k_stats<<<H, 256>>>();
    k_wsum<<<NBLK, 256>>>(X4);
    k_reduce1<<<dim3(16, 16), 128>>>();
    k_reduce2<<<16, 128>>>();
    k_vproj<<<128, 256>>>(Win4, bin);
    k_oproj<<<128, 256>>>(Wo4, bo, out);
}

// round 6
// speedup vs baseline: 2.5449x; 2.5449x over previous
#include <cuda_runtime.h>

#define L 32768
#define E 1024
#define H 8
#define D 128
#define E4 (E/4)          // 256 float4 per row
#define NBLK 256          // blocks in wsum pass (128 rows each)
#define RSQRT_D 0.08838834764831845f   // 1/sqrt(128)

typedef unsigned long long u64;

// ---------------- device scratch (no allocations allowed) ----------------
__device__ float g_q[E];                      // q projection [E]
__device__ float g_s[H][E];                   // s = (Wk_h^T q_h) * rsqrt(D)
__device__ float g_logits[H][L];              // 1 MB
__device__ float g_pmax[H * 8];               // per-segment max
__device__ float g_psum[H * 8];               // per-segment exp-sum (local max)
__device__ float g_partial[NBLK][H][E];       // 8 MB per-block weighted sums
__device__ float g_partial2[16][H][E];        // 512 KB stage-2 partials
__device__ float g_w[H][E];                   // sum a_l x_l per head
__device__ float g_attn[E];                   // Wv @ w + bv (concat heads)

// packed f32x2 helpers (ptxas never auto-fuses FFMA2; PTX-only)
#define FMA2(d, a, b, c) \
    asm("fma.rn.f32x2 %0, %1, %2, %3;" : "=l"(d) : "l"(a), "l"(b), "l"(c))

__device__ __forceinline__ u64 pack2(float a, float b) {
    u64 u; asm("mov.b64 %0, {%1, %2};" : "=l"(u) : "f"(a), "f"(b)); return u;
}
__device__ __forceinline__ float unpack_add(u64 u) {
    float lo, hi; asm("mov.b64 {%0, %1}, %2;" : "=f"(lo), "=f"(hi) : "l"(u));
    return lo + hi;
}

__device__ __forceinline__ float warp_sum(float v) {
    v += __shfl_xor_sync(0xffffffffu, v, 16);
    v += __shfl_xor_sync(0xffffffffu, v, 8);
    v += __shfl_xor_sync(0xffffffffu, v, 4);
    v += __shfl_xor_sync(0xffffffffu, v, 2);
    v += __shfl_xor_sync(0xffffffffu, v, 1);
    return v;
}

// ---------------- K1: q[row] = Wq[row,:]·x0 + bq[row] --------------------
__global__ __launch_bounds__(256) void k_qproj(const float4* __restrict__ W4,
                                               const float4* __restrict__ X4,
                                               const float* __restrict__ bias) {
    int warp = threadIdx.x >> 5, lane = threadIdx.x & 31;
    int row = blockIdx.x * 8 + warp;
    const float4* wr = W4 + (size_t)row * E4;
    float4 a = make_float4(0.f, 0.f, 0.f, 0.f);
    #pragma unroll
    for (int i = 0; i < 8; i++) {
        float4 w = wr[lane + 32 * i];
        float4 x = X4[lane + 32 * i];
        a.x = fmaf(w.x, x.x, a.x); a.y = fmaf(w.y, x.y, a.y);
        a.z = fmaf(w.z, x.z, a.z); a.w = fmaf(w.w, x.w, a.w);
    }
    float acc = warp_sum((a.x + a.y) + (a.z + a.w));
    if (lane == 0) g_q[row] = acc + bias[row];
}

// ---------------- K2: s[h][e] = rsqrtD * sum_d Wk[h*D+d][e] q[h*D+d] ----
__global__ __launch_bounds__(256) void k_sproj(const float* __restrict__ W) {
    int h = blockIdx.x >> 2, eb = blockIdx.x & 3;
    int e = eb * 256 + threadIdx.x;
    __shared__ float qsh[D];
    if (threadIdx.x < D) qsh[threadIdx.x] = g_q[h * D + threadIdx.x];
    __syncthreads();
    const float* Wk = W + (size_t)(E + h * D) * E + e;
    float acc = 0.f;
    #pragma unroll 4
    for (int d = 0; d < D; d++)
        acc = fmaf(Wk[(size_t)d * E], qsh[d], acc);
    g_s[h][e] = acc * RSQRT_D;
}

// ---------------- K3: logits — warp-autonomous, MLP-4, f32x2 -------------
// grid 1024 x 256; block = 8 warps x 4 rows = 32 rows. s[8][1024] in SMEM.
__global__ __launch_bounds__(256, 2) void k_logits(const ulonglong2* __restrict__ X2) {
    __shared__ ulonglong2 ssh[8 * 256];         // 32 KB: all 8 heads' s
    int t = threadIdx.x;
    const ulonglong2* gs2 = (const ulonglong2*)g_s;
    #pragma unroll
    for (int i = 0; i < 8; i++) ssh[t + 256 * i] = gs2[t + 256 * i];
    __syncthreads();

    int w = t >> 5, j = t & 31;
    int base = blockIdx.x * 32 + w * 4;         // this warp's 4 rows

    u64 acc[4][8];
    #pragma unroll
    for (int r = 0; r < 4; r++)
        #pragma unroll
        for (int h = 0; h < H; h++) acc[r][h] = 0ull;

    #pragma unroll
    for (int c = 0; c < 8; c++) {
        int f = j + 32 * c;                     // float4 index within row
        ulonglong2 xv[4];
        #pragma unroll
        for (int r = 0; r < 4; r++)             // 4 independent LDG.128
            xv[r] = X2[(size_t)(base + r) * 256 + f];
        ulonglong2 sv[8];
        #pragma unroll
        for (int h = 0; h < H; h++) sv[h] = ssh[h * 256 + f];
        #pragma unroll
        for (int r = 0; r < 4; r++)
            #pragma unroll
            for (int h = 0; h < H; h++) {
                FMA2(acc[r][h], xv[r].x, sv[h].x, acc[r][h]);
                FMA2(acc[r][h], xv[r].y, sv[h].y, acc[r][h]);
            }
    }
    #pragma unroll
    for (int r = 0; r < 4; r++)
        #pragma unroll
        for (int h = 0; h < H; h++) {
            float v = warp_sum(unpack_add(acc[r][h]));
            if (j == 0) g_logits[h][base + r] = v;
        }
}

// ---------------- K4: partial softmax stats (64 blocks) ------------------
// block = (head h, segment seg of 4096 logits): local max + local expsum.
__global__ __launch_bounds__(256) void k_pstats() {
    int h = blockIdx.x >> 3, seg = blockIdx.x & 7;
    int t = threadIdx.x;
    const float* lg = g_logits[h] + seg * 4096;
    __shared__ float red[8];
    __shared__ float Msh;

    float m = -1e30f;
    #pragma unroll 4
    for (int k = 0; k < 16; k++) m = fmaxf(m, lg[t + 256 * k]);
    #pragma unroll
    for (int o = 16; o; o >>= 1) m = fmaxf(m, __shfl_xor_sync(0xffffffffu, m, o));
    if ((t & 31) == 0) red[t >> 5] = m;
    __syncthreads();
    if (t == 0) {
        float mm = red[0];
        #pragma unroll
        for (int w = 1; w < 8; w++) mm = fmaxf(mm, red[w]);
        Msh = mm;
    }
    __syncthreads();
    float M = Msh;

    float s = 0.f;
    #pragma unroll 4
    for (int k = 0; k < 16; k++) s += __expf(lg[t + 256 * k] - M);
    s = warp_sum(s);
    if ((t & 31) == 0) red[t >> 5] = s;
    __syncthreads();
    if (t == 0) {
        float ss = 0.f;
        #pragma unroll
        for (int w = 0; w < 8; w++) ss += red[w];
        g_pmax[blockIdx.x] = M;
        g_psum[blockIdx.x] = ss;
    }
}

// ---------------- K5: weighted sum — direct-LDG streaming, f32x2 ---------
// grid 256 x 256; block covers 128 rows; thread t owns column float4 e4=t,
// accumulates all 8 heads in registers.
__global__ __launch_bounds__(256) void k_wsum(const ulonglong2* __restrict__ X2) {
    int t = threadIdx.x;
    int b = blockIdx.x;
    int row0 = b * 128;
    __shared__ float M_sh[H], invS_sh[H];
    __shared__ u64 a2[128][H];                  // 8 KB packed weights

    // merge global softmax stats from 8 segments (redundant per block, L2-hot)
    if (t < H) {
        float m = -1e30f;
        #pragma unroll
        for (int k = 0; k < 8; k++) m = fmaxf(m, g_pmax[t * 8 + k]);
        float s = 0.f;
        #pragma unroll
        for (int k = 0; k < 8; k++)
            s += g_psum[t * 8 + k] * __expf(g_pmax[t * 8 + k] - m);
        M_sh[t] = m;
        invS_sh[t] = 1.0f / s;
    }
    __syncthreads();

    #pragma unroll
    for (int i = 0; i < 4; i++) {
        int idx = t + 256 * i;                  // 0..1023
        int hh = idx >> 7, r = idx & 127;       // r-coalesced logits read
        float av = __expf(g_logits[hh][row0 + r] - M_sh[hh]) * invS_sh[hh];
        a2[r][hh] = pack2(av, av);
    }
    __syncthreads();

    u64 acc[H][2];
    #pragma unroll
    for (int h = 0; h < H; h++) { acc[h][0] = 0ull; acc[h][1] = 0ull; }

    #pragma unroll 4
    for (int r = 0; r < 128; r++) {
        ulonglong2 xv = X2[(size_t)(row0 + r) * 256 + t];
        const ulonglong2* ap = (const ulonglong2*)a2[r];
        #pragma unroll
        for (int hp = 0; hp < 4; hp++) {
            ulonglong2 aa = ap[hp];             // heads 2hp, 2hp+1 (broadcast)
            FMA2(acc[2 * hp][0],     aa.x, xv.x, acc[2 * hp][0]);
            FMA2(acc[2 * hp][1],     aa.x, xv.y, acc[2 * hp][1]);
            FMA2(acc[2 * hp + 1][0], aa.y, xv.x, acc[2 * hp + 1][0]);
            FMA2(acc[2 * hp + 1][1], aa.y, xv.y, acc[2 * hp + 1][1]);
        }
    }
    #pragma unroll
    for (int h = 0; h < H; h++) {
        float lo0, hi0, lo1, hi1;
        asm("mov.b64 {%0, %1}, %2;" : "=f"(lo0), "=f"(hi0) : "l"(acc[h][0]));
        asm("mov.b64 {%0, %1}, %2;" : "=f"(lo1), "=f"(hi1) : "l"(acc[h][1]));
        ((float4*)g_partial[b][h])[t] = make_float4(lo0, hi0, lo1, hi1);
    }
}

// ---------------- K6a/K6b: deterministic 2-stage reduction ---------------
__global__ __launch_bounds__(128) void k_reduce1() {
    int out4 = blockIdx.x * 128 + threadIdx.x;  // 0..2047
    int b0 = blockIdx.y * 16;
    const float4* P4 = (const float4*)g_partial;
    float4 acc = make_float4(0.f, 0.f, 0.f, 0.f);
    #pragma unroll 4
    for (int b = b0; b < b0 + 16; b++) {
        float4 v = P4[(size_t)b * (H * E4) + out4];
        acc.x += v.x; acc.y += v.y; acc.z += v.z; acc.w += v.w;
    }
    ((float4*)g_partial2)[(size_t)blockIdx.y * (H * E4) + out4] = acc;
}

__global__ __launch_bounds__(128) void k_reduce2() {
    int out4 = blockIdx.x * 128 + threadIdx.x;
    const float4* P4 = (const float4*)g_partial2;
    float4 acc = make_float4(0.f, 0.f, 0.f, 0.f);
    #pragma unroll
    for (int b = 0; b < 16; b++) {
        float4 v = P4[(size_t)b * (H * E4) + out4];
        acc.x += v.x; acc.y += v.y; acc.z += v.z; acc.w += v.w;
    }
    ((float4*)g_w)[out4] = acc;
}

// ---------------- K7: attn[row] = Wv[row,:]·w_h + bv[row] ----------------
__global__ __launch_bounds__(256) void k_vproj(const float4* __restrict__ W4,
                                               const float* __restrict__ bias) {
    int warp = threadIdx.x >> 5, lane = threadIdx.x & 31;
    int row = blockIdx.x * 8 + warp;
    int h = row >> 7;
    const float4* wr = W4 + (size_t)(2 * E + row) * E4;
    const float4* v4 = (const float4*)g_w[h];
    float4 a = make_float4(0.f, 0.f, 0.f, 0.f);
    #pragma unroll
    for (int i = 0; i < 8; i++) {
        float4 w = wr[lane + 32 * i];
        float4 x = v4[lane + 32 * i];
        a.x = fmaf(w.x, x.x, a.x); a.y = fmaf(w.y, x.y, a.y);
        a.z = fmaf(w.z, x.z, a.z); a.w = fmaf(w.w, x.w, a.w);
    }
    float acc = warp_sum((a.x + a.y) + (a.z + a.w));
    if (lane == 0) g_attn[row] = acc + bias[2 * E + row];
}

// ---------------- K8: out[row] = Wo[row,:]·attn + bo[row] ----------------
__global__ __launch_bounds__(256) void k_oproj(const float4* __restrict__ Wo4,
                                               const float* __restrict__ bo,
                                               float* __restrict__ out) {
    int warp = threadIdx.x >> 5, lane = threadIdx.x & 31;
    int row = blockIdx.x * 8 + warp;
    const float4* wr = Wo4 + (size_t)row * E4;
    const float4* v4 = (const float4*)g_attn;
    float4 a = make_float4(0.f, 0.f, 0.f, 0.f);
    #pragma unroll
    for (int i = 0; i < 8; i++) {
        float4 w = wr[lane + 32 * i];
        float4 x = v4[lane + 32 * i];
        a.x = fmaf(w.x, x.x, a.x); a.y = fmaf(w.y, x.y, a.y);
        a.z = fmaf(w.z, x.z, a.z); a.w = fmaf(w.w, x.w, a.w);
    }
    float acc = warp_sum((a.x + a.y) + (a.z + a.w));
    if (lane == 0) out[row] = acc + bo[row];
}

extern "C" void kernel_launch(void* const* d_in, const int* in_sizes, int n_in,
                              void* d_out, int out_size) {
    const float* x   = (const float*)d_in[0];   // [L, E]
    const float* Win = (const float*)d_in[1];   // [3E, E]
    const float* bin = (const float*)d_in[2];   // [3E]
    const float* Wo  = (const float*)d_in[3];   // [E, E]
    const float* bo  = (const float*)d_in[4];   // [E]
    float* out = (float*)d_out;                 // [1, E]

    const float4* X4 = (const float4*)x;
    const ulonglong2* X2 = (const ulonglong2*)x;
    const float4* Win4 = (const float4*)Win;
    const float4* Wo4 = (const float4*)Wo;

    k_qproj<<<128, 256>>>(Win4, X4, bin);
    k_sproj<<<32, 256>>>(Win);
    k_logits<<<1024, 256>>>(X2);
    k_pstats<<<64, 256>>>();
    k_wsum<<<NBLK, 256>>>(X2);
    k_reduce1<<<dim3(16, 16), 128>>>();
    k_reduce2<<<16, 128>>>();
    k_vproj<<<128, 256>>>(Win4, bin);
    k_oproj<<<128, 256>>>(Wo4, bo, out);
}

// round 7
// speedup vs baseline: 2.9764x; 1.1695x over previous
#include <cuda_runtime.h>

#define L 32768
#define E 1024
#define H 8
#define D 128
#define E4 256            // float4 per row
#define NB 128            // fused blocks (1 wave)
#define RPB 256           // rows per fused block
#define TILE 16
#define NT (RPB/TILE)     // 16 tiles per block
#define RSQRT_D 0.08838834764831845f

typedef unsigned long long u64;

// ---------------- device scratch ----------------
__device__ float g_q[E];
__device__ float g_s[H][E];
__device__ float g_pm[NB * H];
__device__ float g_ps[NB * H];
__device__ float g_partial[NB][H][E];   // 4 MB  (unnormalized, local max)
__device__ float g_partial2[8][H][E];   // 256 KB
__device__ float g_w[H][E];
__device__ float g_attn[E];

#define FMA2(d, a, b, c) \
    asm("fma.rn.f32x2 %0, %1, %2, %3;" : "=l"(d) : "l"(a), "l"(b), "l"(c))

__device__ __forceinline__ u64 pack2(float a, float b) {
    u64 u; asm("mov.b64 %0, {%1, %2};" : "=l"(u) : "f"(a), "f"(b)); return u;
}
__device__ __forceinline__ float unpack_add(u64 u) {
    float lo, hi; asm("mov.b64 {%0, %1}, %2;" : "=f"(lo), "=f"(hi) : "l"(u));
    return lo + hi;
}
__device__ __forceinline__ float warp_sum(float v) {
    v += __shfl_xor_sync(0xffffffffu, v, 16);
    v += __shfl_xor_sync(0xffffffffu, v, 8);
    v += __shfl_xor_sync(0xffffffffu, v, 4);
    v += __shfl_xor_sync(0xffffffffu, v, 2);
    v += __shfl_xor_sync(0xffffffffu, v, 1);
    return v;
}

// ---------------- K1: q = Wq·x0 + bq ----------------
__global__ __launch_bounds__(256) void k_qproj(const float4* __restrict__ W4,
                                               const float4* __restrict__ X4,
                                               const float* __restrict__ bias) {
    int warp = threadIdx.x >> 5, lane = threadIdx.x & 31;
    int row = blockIdx.x * 8 + warp;
    const float4* wr = W4 + (size_t)row * E4;
    float4 a = make_float4(0.f, 0.f, 0.f, 0.f);
    #pragma unroll
    for (int i = 0; i < 8; i++) {
        float4 w = wr[lane + 32 * i];
        float4 x = X4[lane + 32 * i];
        a.x = fmaf(w.x, x.x, a.x); a.y = fmaf(w.y, x.y, a.y);
        a.z = fmaf(w.z, x.z, a.z); a.w = fmaf(w.w, x.w, a.w);
    }
    float acc = warp_sum((a.x + a.y) + (a.z + a.w));
    if (lane == 0) g_q[row] = acc + bias[row];
}

// ---------------- K2: s[h] = rsqrtD * Wk_h^T q_h  (d-split, MLP-8) -------
// grid 32 = (h*4 + seg); thread (dq = t>>6, e4 = seg*64 + t&63)
__global__ __launch_bounds__(256) void k_sproj(const float4* __restrict__ W4) {
    int h = blockIdx.x >> 2, seg = blockIdx.x & 3;
    int t = threadIdx.x;
    int dq = t >> 6, ec = t & 63;
    int e4 = seg * 64 + ec;
    __shared__ float qsh[D];
    __shared__ float4 pacc[4][64];
    if (t < D) qsh[t] = g_q[h * D + t];
    __syncthreads();
    const float4* Wk = W4 + (size_t)(E + h * D + dq * 32) * E4 + e4;
    float4 a = make_float4(0.f, 0.f, 0.f, 0.f);
    #pragma unroll 8
    for (int d = 0; d < 32; d++) {
        float4 w = Wk[(size_t)d * E4];
        float q = qsh[dq * 32 + d];
        a.x = fmaf(w.x, q, a.x); a.y = fmaf(w.y, q, a.y);
        a.z = fmaf(w.z, q, a.z); a.w = fmaf(w.w, q, a.w);
    }
    pacc[dq][ec] = a;
    __syncthreads();
    if (t < 64) {
        float4 r = pacc[0][t];
        #pragma unroll
        for (int k = 1; k < 4; k++) {
            float4 v = pacc[k][t];
            r.x += v.x; r.y += v.y; r.z += v.z; r.w += v.w;
        }
        r.x *= RSQRT_D; r.y *= RSQRT_D; r.z *= RSQRT_D; r.w *= RSQRT_D;
        ((float4*)g_s[h])[seg * 64 + t] = r;
    }
}

// ---------------- K3: fused logits + online softmax + weighted sum -------
struct FSmem {
    ulonglong2 xbuf[2][TILE][E4];   // 128 KB double-buffered X tile
    ulonglong2 ssh[H * E4];         // 32 KB all heads' s
    float plg[2][TILE][H];          // c-half partial logits
    float lgs[TILE][H];             // combined logits
    u64   a2[TILE][H];              // packed exp weights
    float m_run[H], s_run[H], f_sh[H];
};

__device__ __forceinline__ void issue_loads(FSmem* s, int buf,
                                            const float4* __restrict__ X4,
                                            int row_base, int t) {
    #pragma unroll
    for (int i = 0; i < TILE; i++) {
        unsigned sa = (unsigned)__cvta_generic_to_shared(&s->xbuf[buf][i][t]);
        const float4* g = X4 + (size_t)(row_base + i) * E4 + t;
        asm volatile("cp.async.cg.shared.global [%0], [%1], 16;"
                     :: "r"(sa), "l"(g) : "memory");
    }
    asm volatile("cp.async.commit_group;" ::: "memory");
}

__global__ __launch_bounds__(256, 1) void k_fused(const float4* __restrict__ X4) {
    extern __shared__ char smem_raw[];
    FSmem* s = reinterpret_cast<FSmem*>(smem_raw);
    int t = threadIdx.x, w = t >> 5, j = t & 31;
    int b = blockIdx.x;
    int row0 = b * RPB;
    int cg = w >> 2, rg = w & 3;                // c-half, 4-row group

    const ulonglong2* gs2 = (const ulonglong2*)g_s;
    #pragma unroll
    for (int i = 0; i < 8; i++) s->ssh[t + 256 * i] = gs2[t + 256 * i];
    if (t < H) { s->m_run[t] = -1e30f; s->s_run[t] = 0.f; }

    u64 accB[H][2];
    #pragma unroll
    for (int h = 0; h < H; h++) { accB[h][0] = 0ull; accB[h][1] = 0ull; }

    issue_loads(s, 0, X4, row0, t);

    for (int tile = 0; tile < NT; tile++) {
        int buf = tile & 1;
        asm volatile("cp.async.wait_group 0;" ::: "memory");
        __syncthreads();
        if (tile + 1 < NT) issue_loads(s, buf ^ 1, X4, row0 + (tile + 1) * TILE, t);

        // ---- phase A: partial logits, warp = (c-half cg) x (rows rg*4..+3)
        u64 acc[4][H];
        #pragma unroll
        for (int rr = 0; rr < 4; rr++)
            #pragma unroll
            for (int h = 0; h < H; h++) acc[rr][h] = 0ull;
        #pragma unroll
        for (int cc = 0; cc < 4; cc++) {
            int f = j + 32 * (cg * 4 + cc);
            ulonglong2 xv[4];
            #pragma unroll
            for (int rr = 0; rr < 4; rr++) xv[rr] = s->xbuf[buf][rg * 4 + rr][f];
            ulonglong2 sv[H];
            #pragma unroll
            for (int h = 0; h < H; h++) sv[h] = s->ssh[h * 256 + f];
            #pragma unroll
            for (int rr = 0; rr < 4; rr++)
                #pragma unroll
                for (int h = 0; h < H; h++) {
                    FMA2(acc[rr][h], xv[rr].x, sv[h].x, acc[rr][h]);
                    FMA2(acc[rr][h], xv[rr].y, sv[h].y, acc[rr][h]);
                }
        }
        #pragma unroll
        for (int rr = 0; rr < 4; rr++)
            #pragma unroll
            for (int h = 0; h < H; h++) {
                float v = warp_sum(unpack_add(acc[rr][h]));
                if (j == 0) s->plg[cg][rg * 4 + rr][h] = v;
            }
        __syncthreads();

        // ---- stats step 1: per-head running max + rescale factor
        if (t < H) {
            float m_old = s->m_run[t], m_new = m_old;
            #pragma unroll
            for (int r = 0; r < TILE; r++) {
                float z = s->plg[0][r][t] + s->plg[1][r][t];
                s->lgs[r][t] = z;
                m_new = fmaxf(m_new, z);
            }
            s->m_run[t] = m_new;
            s->f_sh[t] = __expf(m_old - m_new);
        }
        __syncthreads();
        // ---- stats step 2: weights + running sum (warps 0..3)
        if (t < 128) {
            int h = t >> 4, r = t & 15;
            float e = __expf(s->lgs[r][h] - s->m_run[h]);
            s->a2[r][h] = pack2(e, e);
            float ss = e;
            ss += __shfl_xor_sync(0xffffffffu, ss, 8);
            ss += __shfl_xor_sync(0xffffffffu, ss, 4);
            ss += __shfl_xor_sync(0xffffffffu, ss, 2);
            ss += __shfl_xor_sync(0xffffffffu, ss, 1);
            if ((t & 15) == 0) s->s_run[h] = s->s_run[h] * s->f_sh[h] + ss;
        }
        __syncthreads();

        // ---- phase B: rescale accumulators, add tile contributions
        #pragma unroll
        for (int h = 0; h < H; h++) {
            u64 fh = pack2(s->f_sh[h], s->f_sh[h]);
            FMA2(accB[h][0], accB[h][0], fh, 0ull);
            FMA2(accB[h][1], accB[h][1], fh, 0ull);
        }
        #pragma unroll 4
        for (int r = 0; r < TILE; r++) {
            ulonglong2 xv = s->xbuf[buf][r][t];
            const ulonglong2* ap = (const ulonglong2*)s->a2[r];
            #pragma unroll
            for (int hp = 0; hp < 4; hp++) {
                ulonglong2 aa = ap[hp];
                FMA2(accB[2 * hp][0],     aa.x, xv.x, accB[2 * hp][0]);
                FMA2(accB[2 * hp][1],     aa.x, xv.y, accB[2 * hp][1]);
                FMA2(accB[2 * hp + 1][0], aa.y, xv.x, accB[2 * hp + 1][0]);
                FMA2(accB[2 * hp + 1][1], aa.y, xv.y, accB[2 * hp + 1][1]);
            }
        }
        // next iteration's top __syncthreads() fences buffer reuse
    }

    #pragma unroll
    for (int h = 0; h < H; h++) {
        ulonglong2 v; v.x = accB[h][0]; v.y = accB[h][1];
        ((ulonglong2*)g_partial[b][h])[t] = v;
    }
    if (t < H) { g_pm[b * H + t] = s->m_run[t]; g_ps[b * H + t] = s->s_run[t]; }
}

// ---------------- K4a: rescale + 16-block group reduce -------------------
// grid (16, 8) x 128; h fixed per block (= bx>>1).
__global__ __launch_bounds__(128) void k_reduce1() {
    int t = threadIdx.x;
    int out4 = blockIdx.x * 128 + t;            // 0..2047
    int h = out4 >> 8;
    int g = blockIdx.y;
    __shared__ float red[4];
    __shared__ float Msh;
    __shared__ float fac[16];

    float m = g_pm[t * H + h];                  // t covers all 128 blocks
    #pragma unroll
    for (int o = 16; o; o >>= 1) m = fmaxf(m, __shfl_xor_sync(0xffffffffu, m, o));
    if ((t & 31) == 0) red[t >> 5] = m;
    __syncthreads();
    if (t == 0) Msh = fmaxf(fmaxf(red[0], red[1]), fmaxf(red[2], red[3]));
    __syncthreads();
    if (t < 16) fac[t] = __expf(g_pm[(g * 16 + t) * H + h] - Msh);
    __syncthreads();

    const float4* P = (const float4*)g_partial;
    float4 acc = make_float4(0.f, 0.f, 0.f, 0.f);
    #pragma unroll
    for (int k = 0; k < 16; k++) {
        float4 v = P[(size_t)(g * 16 + k) * 2048 + out4];
        float f = fac[k];
        acc.x = fmaf(v.x, f, acc.x); acc.y = fmaf(v.y, f, acc.y);
        acc.z = fmaf(v.z, f, acc.z); acc.w = fmaf(v.w, f, acc.w);
    }
    ((float4*)g_partial2)[(size_t)g * 2048 + out4] = acc;
}

// ---------------- K4b: final sum + 1/S normalize -------------------------
__global__ __launch_bounds__(128) void k_reduce2() {
    int t = threadIdx.x;
    int out4 = blockIdx.x * 128 + t;
    int h = out4 >> 8;
    __shared__ float red[4];
    __shared__ float Msh, invSsh;

    float m = g_pm[t * H + h];
    #pragma unroll
    for (int o = 16; o; o >>= 1) m = fmaxf(m, __shfl_xor_sync(0xffffffffu, m, o));
    if ((t & 31) == 0) red[t >> 5] = m;
    __syncthreads();
    if (t == 0) Msh = fmaxf(fmaxf(red[0], red[1]), fmaxf(red[2], red[3]));
    __syncthreads();
    float sp = g_ps[t * H + h] * __expf(g_pm[t * H + h] - Msh);
    sp = warp_sum(sp);
    if ((t & 31) == 0) red[t >> 5] = sp;
    __syncthreads();
    if (t == 0) invSsh = 1.0f / (red[0] + red[1] + red[2] + red[3]);
    __syncthreads();
    float invS = invSsh;

    const float4* P = (const float4*)g_partial2;
    float4 acc = make_float4(0.f, 0.f, 0.f, 0.f);
    #pragma unroll
    for (int g = 0; g < 8; g++) {
        float4 v = P[(size_t)g * 2048 + out4];
        acc.x += v.x; acc.y += v.y; acc.z += v.z; acc.w += v.w;
    }
    acc.x *= invS; acc.y *= invS; acc.z *= invS; acc.w *= invS;
    ((float4*)g_w)[out4] = acc;
}

// ---------------- K5: attn = Wv·w + bv ----------------
__global__ __launch_bounds__(256) void k_vproj(const float4* __restrict__ W4,
                                               const float* __restrict__ bias) {
    int warp = threadIdx.x >> 5, lane = threadIdx.x & 31;
    int row = blockIdx.x * 8 + warp;
    int h = row >> 7;
    const float4* wr = W4 + (size_t)(2 * E + row) * E4;
    const float4* v4 = (const float4*)g_w[h];
    float4 a = make_float4(0.f, 0.f, 0.f, 0.f);
    #pragma unroll
    for (int i = 0; i < 8; i++) {
        float4 w = wr[lane + 32 * i];
        float4 x = v4[lane + 32 * i];
        a.x = fmaf(w.x, x.x, a.x); a.y = fmaf(w.y, x.y, a.y);
        a.z = fmaf(w.z, x.z, a.z); a.w = fmaf(w.w, x.w, a.w);
    }
    float acc = warp_sum((a.x + a.y) + (a.z + a.w));
    if (lane == 0) g_attn[row] = acc + bias[2 * E + row];
}

// ---------------- K6: out = Wo·attn + bo ----------------
__global__ __launch_bounds__(256) void k_oproj(const float4* __restrict__ Wo4,
                                               const float* __restrict__ bo,
                                               float* __restrict__ out) {
    int warp = threadIdx.x >> 5, lane = threadIdx.x & 31;
    int row = blockIdx.x * 8 + warp;
    const float4* wr = Wo4 + (size_t)row * E4;
    const float4* v4 = (const float4*)g_attn;
    float4 a = make_float4(0.f, 0.f, 0.f, 0.f);
    #pragma unroll
    for (int i = 0; i < 8; i++) {
        float4 w = wr[lane + 32 * i];
        float4 x = v4[lane + 32 * i];
        a.x = fmaf(w.x, x.x, a.x); a.y = fmaf(w.y, x.y, a.y);
        a.z = fmaf(w.z, x.z, a.z); a.w = fmaf(w.w, x.w, a.w);
    }
    float acc = warp_sum((a.x + a.y) + (a.z + a.w));
    if (lane == 0) out[row] = acc + bo[row];
}

extern "C" void kernel_launch(void* const* d_in, const int* in_sizes, int n_in,
                              void* d_out, int out_size) {
    const float* x   = (const float*)d_in[0];   // [L, E]
    const float* Win = (const float*)d_in[1];   // [3E, E]
    const float* bin = (const float*)d_in[2];   // [3E]
    const float* Wo  = (const float*)d_in[3];   // [E, E]
    const float* bo  = (const float*)d_in[4];   // [E]
    float* out = (float*)d_out;

    const float4* X4   = (const float4*)x;
    const float4* Win4 = (const float4*)Win;
    const float4* Wo4  = (const float4*)Wo;

    static int smem_set = 0;
    if (!smem_set) {
        cudaFuncSetAttribute(k_fused, cudaFuncAttributeMaxDynamicSharedMemorySize,
                             (int)sizeof(FSmem));
        smem_set = 1;
    }

    k_qproj<<<128, 256>>>(Win4, X4, bin);
    k_sproj<<<32, 256>>>(Win4);
    k_fused<<<NB, 256, sizeof(FSmem)>>>(X4);
    k_reduce1<<<dim3(16, 8), 128>>>();
    k_reduce2<<<16, 128>>>();
    k_vproj<<<128, 256>>>(Win4, bin);
    k_oproj<<<128, 256>>>(Wo4, bo, out);
}